// round 15
// baseline (speedup 1.0000x reference)
#include <cuda_runtime.h>
#include <cuda_fp8.h>
#include <cstdint>

// Problem shape (fixed by the dataset)
#define M_DIM 4096
#define K_DIM 4096
#define N_DIM 11008
#define QW 2048   // qweight int32 words per output row (K/2)

// Scratch (no allocs allowed): fp8 operand planes + row sums
// g_xhi bytes = e4m3(16*(q>>4))  (multiples of 16, exact)
// g_xlo bytes = e4m3(q & 15)     (0..15, exact)
// g_w8  bytes = e4m3(w)          (0..15, exact)
__device__ uint8_t g_xhi[(size_t)M_DIM * K_DIM];   // 16 MB
__device__ uint8_t g_xlo[(size_t)M_DIM * K_DIM];   // 16 MB
__device__ uint8_t g_w8 [(size_t)N_DIM * K_DIM];   // 45 MB
__device__ int g_rowsum[M_DIM];

// ---------------------------------------------------------------------------
// PTX helpers
// ---------------------------------------------------------------------------
__device__ __forceinline__ void cp16(uint32_t dst, const void* src) {
    asm volatile("cp.async.cg.shared.global [%0], [%1], 16;" :: "r"(dst), "l"(src));
}
#define CP_COMMIT() asm volatile("cp.async.commit_group;")
__device__ __forceinline__ void ldsm4(int& r0, int& r1, int& r2, int& r3, uint32_t addr) {
    asm volatile("ldmatrix.sync.aligned.m8n8.x4.shared.b16 {%0,%1,%2,%3}, [%4];"
                 : "=r"(r0), "=r"(r1), "=r"(r2), "=r"(r3) : "r"(addr));
}
// fp8 e4m3 MMA, k32, f32 accumulate
__device__ __forceinline__ void mma_fp8(float* d, const int* a, int b0, int b1) {
    asm volatile("mma.sync.aligned.m16n8k32.row.col.f32.e4m3.e4m3.f32 "
                 "{%0,%1,%2,%3}, {%4,%5,%6,%7}, {%8,%9}, {%0,%1,%2,%3};"
                 : "+f"(d[0]), "+f"(d[1]), "+f"(d[2]), "+f"(d[3])
                 : "r"(a[0]), "r"(a[1]), "r"(a[2]), "r"(a[3]), "r"(b0), "r"(b1));
}
__device__ __forceinline__ uint32_t to_fp8(float f) {
    return (uint32_t)__nv_cvt_float_to_fp8(f, __NV_SATFINITE, __NV_E4M3);
}

// ---------------------------------------------------------------------------
// Kernel 1: static fake-quant of x -> two exact e4m3 planes + per-row sums.
// Thread t handles k [16t, 16t+16) of row blockIdx.x.
// ---------------------------------------------------------------------------
__global__ __launch_bounds__(256) void quantize_kernel(const float* __restrict__ x,
                                                       const float* __restrict__ clampv) {
    const int m = blockIdx.x;
    const float cv = clampv[0];
    const float a_scale = cv / 127.0f;
    const float* xrow = x + (size_t)m * K_DIM;
    const int t = threadIdx.x;

    int q[16];
#pragma unroll
    for (int i = 0; i < 4; i++) {
        float4 v = *reinterpret_cast<const float4*>(xrow + 16 * t + 4 * i);
        q[4 * i + 0] = __float2int_rn(fminf(fmaxf(v.x, -cv), cv) / a_scale);
        q[4 * i + 1] = __float2int_rn(fminf(fmaxf(v.y, -cv), cv) / a_scale);
        q[4 * i + 2] = __float2int_rn(fminf(fmaxf(v.z, -cv), cv) / a_scale);
        q[4 * i + 3] = __float2int_rn(fminf(fmaxf(v.w, -cv), cv) / a_scale);
    }
    int local_sum = 0;
#pragma unroll
    for (int i = 0; i < 16; i++) local_sum += q[i];

    uint32_t hw[4], lw[4];
#pragma unroll
    for (int c = 0; c < 4; c++) {
        uint32_t h = 0, l = 0;
#pragma unroll
        for (int j = 0; j < 4; j++) {
            const int v = q[4 * c + j];
            const int lo = v & 15;
            h |= to_fp8((float)(v - lo)) << (8 * j);   // 16*(v>>4), e4m3-exact
            l |= to_fp8((float)lo) << (8 * j);         // 0..15, e4m3-exact
        }
        hw[c] = h;
        lw[c] = l;
    }
    const size_t off = (size_t)m * K_DIM + 16 * t;
    *reinterpret_cast<int4*>(g_xhi + off) = *reinterpret_cast<int4*>(hw);
    *reinterpret_cast<int4*>(g_xlo + off) = *reinterpret_cast<int4*>(lw);

    int s = local_sum;
#pragma unroll
    for (int off2 = 16; off2 > 0; off2 >>= 1) s += __shfl_down_sync(0xFFFFFFFFu, s, off2);
    __shared__ int wsum[8];
    const int lane = threadIdx.x & 31, wid = threadIdx.x >> 5;
    if (lane == 0) wsum[wid] = s;
    __syncthreads();
    if (threadIdx.x == 0) {
        int tot = 0;
#pragma unroll
        for (int i = 0; i < 8; i++) tot += wsum[i];
        g_rowsum[m] = tot;
    }
}

// ---------------------------------------------------------------------------
// Kernel 2: unpack int4 nibbles -> exact e4m3 weights.
// qword j holds one byte: k=2j from hi nibble, k=2j+1 from lo nibble.
// Thread t handles qwords 8t..8t+7 -> k [16t, 16t+16).
// ---------------------------------------------------------------------------
__global__ __launch_bounds__(256) void unpack_kernel(const int* __restrict__ qweight) {
    const int o = blockIdx.x;
    const int t = threadIdx.x;
    const int* qrow = qweight + (size_t)o * QW + 8 * t;
    int4 q0 = *reinterpret_cast<const int4*>(qrow);
    int4 q1 = *reinterpret_cast<const int4*>(qrow + 4);
    int qv[8] = {q0.x, q0.y, q0.z, q0.w, q1.x, q1.y, q1.z, q1.w};

    uint32_t w[4];
#pragma unroll
    for (int c = 0; c < 4; c++) {
        const int va = qv[2 * c], vb = qv[2 * c + 1];
        w[c] = to_fp8((float)((va >> 4) & 15))
             | to_fp8((float)(va & 15)) << 8
             | to_fp8((float)((vb >> 4) & 15)) << 16
             | to_fp8((float)(vb & 15)) << 24;
    }
    *reinterpret_cast<int4*>(g_w8 + (size_t)o * K_DIM + 16 * t) = *reinterpret_cast<int4*>(w);
}

// ---------------------------------------------------------------------------
// Kernel 3: fp8 QMMA GEMM, exact integer math via hi/lo activation split.
// Block tile 128x128, BK=64 bytes (2 k32 steps), 8 warps (4Mx2N),
// warp tile 32x64. Double-buffered cp.async; 80-byte smem rows (conflict-free,
// proven R3); R3-validated 8-bit ldmatrix fragment mappings.
// ---------------------------------------------------------------------------
#define LDSS 80
#define TILE (128 * LDSS)           // 10240 B per operand tile
#define STG  (3 * TILE)             // A_hi + A_lo + B per stage
#define NCHUNK (K_DIM / 64)         // 64

__global__ __launch_bounds__(256, 2) void gemm_kernel(const int* __restrict__ qzeros,
                                                      const float* __restrict__ scales,
                                                      const float* __restrict__ bias,
                                                      const float* __restrict__ clampv,
                                                      float* __restrict__ out) {
    extern __shared__ __align__(128) char smem[];
    const uint32_t sb = (uint32_t)__cvta_generic_to_shared(smem);

    const int tid = threadIdx.x;
    const int wid = tid >> 5, lane = tid & 31;
    const int wm = wid & 3, wn = wid >> 2;           // 4 warps in M, 2 in N
    const int m0 = blockIdx.y * 128, n0 = blockIdx.x * 128;

    // A ldmatrix addressing (8-bit k32 frag): row-half on bit3, k-half on bit4
    const int lrA = (lane & 7) + ((lane >> 3) & 1) * 8;
    const int lkA = (lane >> 4) * 16;
    // B ldmatrix addressing: k-half on bit3, n-octet on bit4
    const int lrB = (lane & 7) + ((lane >> 4) << 3);
    const int lkB = ((lane >> 3) & 1) * 16;
    const uint32_t a_off = (uint32_t)((wm * 32 + lrA) * LDSS + lkA);
    const uint32_t b_off = (uint32_t)((wn * 64 + lrB) * LDSS + lkB);

    // cp.async mapping: per tile 512 cp16; idx = tid + 256*i -> r=idx>>2, c=idx&3
    const int ldr = tid >> 2, ldc = tid & 3;

    float acc[2][8][4];
#pragma unroll
    for (int mt = 0; mt < 2; mt++)
#pragma unroll
        for (int nt = 0; nt < 8; nt++)
#pragma unroll
            for (int r = 0; r < 4; r++) acc[mt][nt][r] = 0.0f;

    auto load_chunk = [&](int kt, int stage) {
        const uint32_t hb = sb + stage * STG;
        const uint32_t lb = hb + TILE;
        const uint32_t bb = lb + TILE;
        const size_t koff = (size_t)kt * 64 + ldc * 16;
#pragma unroll
        for (int i = 0; i < 2; i++) {
            const int r = ldr + 64 * i;
            const uint32_t sw = (uint32_t)(r * LDSS + ldc * 16);
            cp16(hb + sw, g_xhi + (size_t)(m0 + r) * K_DIM + koff);
            cp16(lb + sw, g_xlo + (size_t)(m0 + r) * K_DIM + koff);
            cp16(bb + sw, g_w8  + (size_t)(n0 + r) * K_DIM + koff);
        }
        CP_COMMIT();
    };

    load_chunk(0, 0);

#pragma unroll 1
    for (int kt = 0; kt < NCHUNK; kt++) {
        if (kt + 1 < NCHUNK) {
            load_chunk(kt + 1, (kt + 1) & 1);
            asm volatile("cp.async.wait_group 1;");
        } else {
            asm volatile("cp.async.wait_group 0;");
        }
        __syncthreads();

        const uint32_t hb = sb + (kt & 1) * STG;
        const uint32_t lb = hb + TILE;
        const uint32_t bb = lb + TILE;
#pragma unroll
        for (int ks = 0; ks < 2; ks++) {            // two k32 steps per 64B chunk
            int ah[2][4], al[2][4], b[4][4];
            ldsm4(ah[0][0], ah[0][1], ah[0][2], ah[0][3], hb + a_off + ks * 32);
            ldsm4(ah[1][0], ah[1][1], ah[1][2], ah[1][3], hb + a_off + ks * 32 + 16 * LDSS);
            ldsm4(al[0][0], al[0][1], al[0][2], al[0][3], lb + a_off + ks * 32);
            ldsm4(al[1][0], al[1][1], al[1][2], al[1][3], lb + a_off + ks * 32 + 16 * LDSS);
#pragma unroll
            for (int p = 0; p < 4; p++)
                ldsm4(b[p][0], b[p][1], b[p][2], b[p][3],
                      bb + b_off + ks * 32 + p * 16 * LDSS);
#pragma unroll
            for (int mt = 0; mt < 2; mt++)
#pragma unroll
                for (int nt = 0; nt < 8; nt++) {
                    const int b0 = b[nt >> 1][(nt & 1) * 2];
                    const int b1 = b[nt >> 1][(nt & 1) * 2 + 1];
                    mma_fp8(acc[mt][nt], ah[mt], b0, b1);
                    mma_fp8(acc[mt][nt], al[mt], b0, b1);
                }
        }
        __syncthreads();
    }

    // ---- epilogue: out = sc*(acc - z*rowsum) + bias (all exact integers)
    const float cv = clampv[0];
    const float a_scale = cv / 127.0f;
    const int g = lane >> 2, tg = lane & 3;

    float scf[8][2], bif[8][2], zzf[8][2];
#pragma unroll
    for (int nt = 0; nt < 8; nt++) {
        const int col = n0 + wn * 64 + nt * 8 + tg * 2;
#pragma unroll
        for (int j = 0; j < 2; j++) {
            scf[nt][j] = scales[col + j] * a_scale;
            zzf[nt][j] = (float)qzeros[col + j];
            bif[nt][j] = bias[col + j];
        }
    }

#pragma unroll
    for (int mt = 0; mt < 2; mt++)
#pragma unroll
        for (int h = 0; h < 2; h++) {
            const int row = m0 + wm * 32 + mt * 16 + h * 8 + g;
            const float rs = (float)g_rowsum[row];
            float* orow = out + (size_t)row * N_DIM + n0 + wn * 64;
#pragma unroll
            for (int nt = 0; nt < 8; nt++) {
                float2 v;
                v.x = scf[nt][0] * (acc[mt][nt][h * 2 + 0] - zzf[nt][0] * rs) + bif[nt][0];
                v.y = scf[nt][1] * (acc[mt][nt][h * 2 + 1] - zzf[nt][1] * rs) + bif[nt][1];
                *reinterpret_cast<float2*>(orow + nt * 8 + tg * 2) = v;
            }
        }
}

// ---------------------------------------------------------------------------
extern "C" void kernel_launch(void* const* d_in, const int* in_sizes, int n_in,
                              void* d_out, int out_size) {
    const float* x       = (const float*)d_in[0];   // [4096, 4096] f32
    const int*   qweight = (const int*)  d_in[1];   // [11008, 2048] i32
    const int*   qzeros  = (const int*)  d_in[2];   // [11008, 1] i32
    const float* scales  = (const float*)d_in[3];   // [11008, 1] f32
    const float* bias    = (const float*)d_in[4];   // [11008] f32
    const float* clampv  = (const float*)d_in[5];   // [1] f32
    float* out = (float*)d_out;                     // [4096, 11008] f32

    cudaFuncSetAttribute(gemm_kernel, cudaFuncAttributeMaxDynamicSharedMemorySize, 2 * STG);

    quantize_kernel<<<M_DIM, 256>>>(x, clampv);
    unpack_kernel<<<N_DIM, 256>>>(qweight);
    gemm_kernel<<<dim3(N_DIM / 128, M_DIM / 128), 256, 2 * STG>>>(qzeros, scales, bias,
                                                                  clampv, out);
}